// round 12
// baseline (speedup 1.0000x reference)
#include <cuda_runtime.h>

// Problem dims
#define N_   32
#define C_   256
#define H_   56
#define W_   56
#define HW_  (H_ * W_)          // 3136
#define NP_  (N_ * HW_)         // 100352 pixels
#define QUADS (NP_ / 4)         // 25088 pixel-quads
#define OCTS  (NP_ / 8)         // 12544 pixel-octs
#define KW_CAP 2304             // max deviants per output channel (C_*9)

#define CCHUNKS 8               // csum channel chunks (32 ch each)
#define CPER    (C_ / CCHUNKS)  // 32
#define OCHUNK  8               // channels per thread in k_out (two 4-ch batches)
#define BOX_BLOCK 128
#define BOX_GRID (QUADS / BOX_BLOCK)   // 196 (exact)
#define CSUM_BLOCKS (OCTS / 256)       // 49 per chunk (oct threads)
#define CSUM_TOTAL  (CSUM_BLOCKS * CCHUNKS)  // 392
#define OUT_BLOCKS  (OCTS / 256)       // 49 (exact)

// ---------------- scratch (static device) -----------------------------------
__device__ float  g_sum[NP_];            // accumulated per-pixel channel sum
__device__ float  g_S[NP_];              // 3x3 box sum
__device__ double g_p1[BOX_GRID], g_p2[BOX_GRID];  // per-block stats partials
__device__ int    g_devList[C_ * KW_CAP];
__device__ int    g_devCnt[C_];          // plain-stored each run by wscan
__device__ int    g_anyDev;              // written by k_box last block
__device__ float  g_a[C_], g_b[C_];      // fused BN scale/shift
__device__ unsigned int g_ticket;        // = 0 initially; self-restores to 0

__device__ __forceinline__ float sgn(float v) {
    return (float)((v > 0.0f) - (v < 0.0f));
}

// ---- L2-policy accesses: ALL evict hints require 256-bit (.v8.b32) on sm_103a.
__device__ __forceinline__ void ldg_evict_last8(const float* p, float* v) {
    asm volatile("ld.global.nc.L2::evict_last.v8.b32 {%0,%1,%2,%3,%4,%5,%6,%7}, [%8];"
                 : "=f"(v[0]), "=f"(v[1]), "=f"(v[2]), "=f"(v[3]),
                   "=f"(v[4]), "=f"(v[5]), "=f"(v[6]), "=f"(v[7]) : "l"(p));
}
__device__ __forceinline__ void ldg_evict_first8(const float* p, float* v) {
    asm volatile("ld.global.nc.L2::evict_first.v8.b32 {%0,%1,%2,%3,%4,%5,%6,%7}, [%8];"
                 : "=f"(v[0]), "=f"(v[1]), "=f"(v[2]), "=f"(v[3]),
                   "=f"(v[4]), "=f"(v[5]), "=f"(v[6]), "=f"(v[7]) : "l"(p));
}
__device__ __forceinline__ void stg_evict_first8(float* p, const float* v) {
    asm volatile("st.global.L2::evict_first.v8.b32 [%0], {%1,%2,%3,%4,%5,%6,%7,%8};"
                 :: "l"(p), "f"(v[0]), "f"(v[1]), "f"(v[2]), "f"(v[3]),
                    "f"(v[4]), "f"(v[5]), "f"(v[6]), "f"(v[7]) : "memory");
}

// ---------------- kernel 1: csum (392 blocks) + wscan (256 blocks), fused ---
__global__ void __launch_bounds__(256) k_csum_wscan(const float* __restrict__ x,
                                                    const float* __restrict__ w) {
    int b = blockIdx.x;
    if (b < CSUM_TOTAL) {
        int pl = b / CSUM_BLOCKS;
        int q  = (b - pl * CSUM_BLOCKS) * 256 + threadIdx.x;   // oct index, exact
        int p8 = q * 8;
        int n  = p8 / HW_;
        int hw = p8 - n * HW_;
        const float* xp = x + ((size_t)n * C_ + pl * CPER) * HW_ + hw;
        float acc[8] = {0.f, 0.f, 0.f, 0.f, 0.f, 0.f, 0.f, 0.f};
#pragma unroll
        for (int c = 0; c < CPER; c++) {
            float v[8];
            ldg_evict_last8(xp + (size_t)c * HW_, v);   // keep x L2-resident
#pragma unroll
            for (int l = 0; l < 8; l++) acc[l] += sgn(v[l]);
        }
        // accumulate into single plane (exact: integer-valued floats)
#pragma unroll
        for (int l = 0; l < 8; l++)
            atomicAdd(&g_sum[p8 + l], acc[l]);
        return;
    }
    // ---- weight-deviant compaction, one block per output channel ----
    __shared__ int cnt;
    int o = b - CSUM_TOTAL;
    if (threadIdx.x == 0) cnt = 0;
    __syncthreads();
    const float* wo = w + (size_t)o * (C_ * 9);
#pragma unroll
    for (int j = 0; j < 9; j++) {
        int i = threadIdx.x * 9 + j;         // i < 2304
        float v = wo[i];
        int s = (v > 0.0f) - (v < 0.0f);     // jnp.sign
        int delta = s - 1;
        if (delta != 0) {
            int c = i / 9, k = i - c * 9;
            int slot = atomicAdd(&cnt, 1);   // shared atomic only
            g_devList[o * KW_CAP + slot] = (c << 6) | (k << 2) | (delta + 2);
        }
    }
    __syncthreads();
    if (threadIdx.x == 0) g_devCnt[o] = cnt;
}

__device__ __forceinline__ float signx_at(const float* __restrict__ x,
                                          int n, int c, int hh, int ww) {
    if (hh < 0 || hh >= H_ || ww < 0 || ww >= W_) return 0.0f;
    float v = x[((size_t)n * C_ + c) * HW_ + hh * W_ + ww];
    return sgn(v);
}

// ---------------- kernel 2: 3x3 box over SINGLE plane + stats + params ------
__global__ void __launch_bounds__(BOX_BLOCK) k_box(const float* __restrict__ x,
                                                   const float* __restrict__ gamma,
                                                   const float* __restrict__ beta) {
    int q  = blockIdx.x * BOX_BLOCK + threadIdx.x;   // exact: 196*128 = QUADS
    int p4 = q * 4;
    int n  = p4 / HW_;
    int hw = p4 - n * HW_;
    int h  = hw / W_, w0 = hw - h * W_;              // w0 % 4 == 0

    float v0 = 0.f, v1 = 0.f, v2 = 0.f, v3 = 0.f, v4 = 0.f, v5 = 0.f;
    const float* base = g_sum + n * HW_;
#pragma unroll
    for (int dh = -1; dh <= 1; dh++) {
        int hh = h + dh;
        if ((unsigned)hh < (unsigned)H_) {
            const float* r = base + hh * W_;
            if (w0 > 0)       v0 += r[w0 - 1];
            float4 m = *reinterpret_cast<const float4*>(r + w0);
            v1 += m.x; v2 += m.y; v3 += m.z; v4 += m.w;
            if (w0 + 4 < W_)  v5 += r[w0 + 4];
        }
    }
    float S0 = v0 + v1 + v2;
    float S1 = v1 + v2 + v3;
    float S2 = v2 + v3 + v4;
    float S3 = v3 + v4 + v5;
    float4 o; o.x = S0; o.y = S1; o.z = S2; o.w = S3;
    *reinterpret_cast<float4*>(g_S + p4) = o;

    // block stats partials (double, plain store)
    double s1 = (double)S0 + (double)S1 + (double)S2 + (double)S3;
    double s2 = (double)S0 * S0 + (double)S1 * S1 + (double)S2 * S2 + (double)S3 * S3;
#pragma unroll
    for (int off = 16; off > 0; off >>= 1) {
        s1 += __shfl_xor_sync(0xffffffffu, s1, off);
        s2 += __shfl_xor_sync(0xffffffffu, s2, off);
    }
    __shared__ double w1[4], w2[4];
    int lane = threadIdx.x & 31, warp = threadIdx.x >> 5;
    if (lane == 0) { w1[warp] = s1; w2[warp] = s2; }
    __syncthreads();
    __shared__ bool isLast;
    if (threadIdx.x == 0) {
        g_p1[blockIdx.x] = w1[0] + w1[1] + w1[2] + w1[3];
        g_p2[blockIdx.x] = w2[0] + w2[1] + w2[2] + w2[3];
        __threadfence();
        unsigned int t = atomicAdd(&g_ticket, 1u);
        isLast = (t == BOX_GRID - 1);
        if (isLast) g_ticket = 0;            // self-restore for graph replay
    }
    __syncthreads();
    if (!isLast) return;

    // ---- last block: reduce 196 partials, write BN params ----
    int t = threadIdx.x;
    __shared__ double r1[BOX_BLOCK], r2[BOX_BLOCK];
    double a1 = 0.0, a2 = 0.0;
    for (int i = t; i < BOX_GRID; i += BOX_BLOCK) { a1 += g_p1[i]; a2 += g_p2[i]; }
    r1[t] = a1; r2[t] = a2;
    __syncthreads();
#pragma unroll
    for (int off = BOX_BLOCK / 2; off > 0; off >>= 1) {
        if (t < off) { r1[t] += r1[t + off]; r2[t] += r2[t + off]; }
        __syncthreads();
    }
    double baseSum = r1[0], baseSum2 = r2[0];

    __shared__ int anyDev;
    if (t == 0) anyDev = 0;
    __syncthreads();
    if (t < 128) {
        if (g_devCnt[t] != 0 || g_devCnt[t + 128] != 0) atomicAdd(&anyDev, 1);
    }
    __syncthreads();
    if (t == 0) g_anyDev = anyDev;

    const double M = (double)NP_;
#pragma unroll
    for (int rep = 0; rep < C_ / BOX_BLOCK; rep++) {   // 2 channels per thread
        int c = rep * BOX_BLOCK + t;
        double c1 = 0.0, c2 = 0.0, c3 = 0.0;
        int cnt = g_devCnt[c];
        if (cnt != 0) {                      // never-taken serial fallback
            const int* list = g_devList + c * KW_CAP;
            for (int p = 0; p < NP_; p++) {
                int nn = p / HW_;
                int phw = p - nn * HW_;
                int ph = phw / W_, pw = phw - (phw / W_) * W_;
                float corr = 0.0f;
                for (int j = 0; j < cnt; j++) {
                    int e = list[j];
                    int cin = e >> 6;
                    int k   = (e >> 2) & 15;
                    float delta = (float)((e & 3) - 2);
                    corr += delta * signx_at(x, nn, cin, ph + k / 3 - 1, pw + k % 3 - 1);
                }
                c1 += (double)corr;
                c2 += (double)g_S[p] * (double)corr;
                c3 += (double)corr * (double)corr;
            }
        }
        double mean = (baseSum + c1) / M;
        double ex2  = (baseSum2 + 2.0 * c2 + c3) / M;
        double var  = ex2 - mean * mean;
        float a = gamma[c] * (float)(1.0 / sqrt(var + 1e-5));
        g_a[c] = a;
        g_b[c] = beta[c] - a * (float)mean;
    }
}

// ---------------- kernel 3: normalize + residual (256-bit, 2x4 pipelined) ---
// grid (49, C_/OCHUNK): one 8-float g_S oct serves OCHUNK=8 channels in two
// software-pipelined 4-channel batches.
__global__ void __launch_bounds__(256) k_out(const float* __restrict__ x,
                                             float* __restrict__ out) {
    int q = blockIdx.x * 256 + threadIdx.x;      // oct index, exact grid
    int c0 = blockIdx.y * OCHUNK;
    int p8 = q * 8;
    int n  = p8 / HW_;
    int hw = p8 - n * HW_;

    if (blockIdx.y == 0) {                       // reset accumulator plane
        float4 z; z.x = 0.f; z.y = 0.f; z.z = 0.f; z.w = 0.f;
        *reinterpret_cast<float4*>(g_sum + p8)     = z;
        *reinterpret_cast<float4*>(g_sum + p8 + 4) = z;
    }

    float Ss[8];
    *reinterpret_cast<float4*>(Ss)     = *reinterpret_cast<const float4*>(g_S + p8);
    *reinterpret_cast<float4*>(Ss + 4) = *reinterpret_cast<const float4*>(g_S + p8 + 4);
    size_t base = ((size_t)n * C_ + c0) * HW_ + hw;

    if (g_anyDev == 0) {
        // ---- fast path: two pipelined 4-channel batches of 256-bit accesses
        float xs0[4][8], xs1[4][8];
#pragma unroll
        for (int cc = 0; cc < 4; cc++)
            ldg_evict_first8(x + base + (size_t)cc * HW_, xs0[cc]);
#pragma unroll
        for (int cc = 0; cc < 4; cc++)
            ldg_evict_first8(x + base + (size_t)(cc + 4) * HW_, xs1[cc]);
        float av[8], bv[8];
#pragma unroll
        for (int cc = 0; cc < 8; cc++) { av[cc] = g_a[c0 + cc]; bv[cc] = g_b[c0 + cc]; }
#pragma unroll
        for (int cc = 0; cc < 4; cc++) {
            float a = av[cc], b = bv[cc];
            float o8[8];
#pragma unroll
            for (int l = 0; l < 8; l++)
                o8[l] = fmaf(a, Ss[l], b) + xs0[cc][l];
            stg_evict_first8(out + base + (size_t)cc * HW_, o8);
        }
#pragma unroll
        for (int cc = 0; cc < 4; cc++) {
            float a = av[cc + 4], b = bv[cc + 4];
            float o8[8];
#pragma unroll
            for (int l = 0; l < 8; l++)
                o8[l] = fmaf(a, Ss[l], b) + xs1[cc][l];
            stg_evict_first8(out + base + (size_t)(cc + 4) * HW_, o8);
        }
        return;
    }

    // ---- slow path (weight deviants exist) ----
    for (int cc = 0; cc < OCHUNK; cc++) {
        int c = c0 + cc;
        float a = g_a[c], b = g_b[c];
        float Sc[8];
#pragma unroll
        for (int l = 0; l < 8; l++) Sc[l] = Ss[l];
        int cnt = g_devCnt[c];
        if (cnt != 0) {
            const int* list = g_devList + c * KW_CAP;
            int h = hw / W_, w0 = hw - (hw / W_) * W_;
            for (int j = 0; j < cnt; j++) {
                int e = list[j];
                int cin = e >> 6;
                int k   = (e >> 2) & 15;
                float delta = (float)((e & 3) - 2);
                int dh = k / 3 - 1, dw = k % 3 - 1;
#pragma unroll
                for (int l = 0; l < 8; l++)
                    Sc[l] += delta * signx_at(x, n, cin, h + dh, w0 + l + dw);
            }
        }
        size_t idx = base + (size_t)cc * HW_;
#pragma unroll
        for (int l = 0; l < 8; l++)
            out[idx + l] = fmaf(a, Sc[l], b) + x[idx + l];
    }
}

// ---------------- launch -----------------------------------------------------
extern "C" void kernel_launch(void* const* d_in, const int* in_sizes, int n_in,
                              void* d_out, int out_size) {
    const float* x     = (const float*)d_in[0];
    const float* w     = (const float*)d_in[1];
    const float* gamma = (const float*)d_in[2];
    const float* beta  = (const float*)d_in[3];
    float* out = (float*)d_out;

    k_csum_wscan<<<CSUM_TOTAL + C_, 256>>>(x, w);   // 648 blocks
    k_box<<<BOX_GRID, BOX_BLOCK>>>(x, gamma, beta); // 196 x 128, exact
    {
        dim3 grid(OUT_BLOCKS, C_ / OCHUNK);         // (49, 32), exact
        k_out<<<grid, 256>>>(x, out);
    }
}

// round 13
// speedup vs baseline: 1.0394x; 1.0394x over previous
#include <cuda_runtime.h>

// Problem dims
#define N_   32
#define C_   256
#define H_   56
#define W_   56
#define HW_  (H_ * W_)          // 3136
#define NP_  (N_ * HW_)         // 100352 pixels
#define QUADS (NP_ / 4)         // 25088 pixel-quads
#define OCTS  (NP_ / 8)         // 12544 pixel-octs
#define KW_CAP 2304             // max deviants per output channel (C_*9)

#define CCHUNKS 8               // csum channel chunks (32 ch each)
#define CPER    (C_ / CCHUNKS)  // 32
#define OCHUNK  4               // channels per thread in k_out (8-wide vectors)
#define BOX_BLOCK 128
#define BOX_GRID (QUADS / BOX_BLOCK)   // 196 (exact)
#define CSUM_BLOCKS (OCTS / 256)       // 49 per chunk (oct threads)
#define CSUM_TOTAL  (CSUM_BLOCKS * CCHUNKS)  // 392
#define OUT_BLOCKS  (OCTS / 256)       // 49 (exact)

// ---------------- scratch (static device) -----------------------------------
// g_sum: zero-initialized at load; csum accumulates with vector REDs (exact:
// small integer-valued floats); k_out re-zeroes it at the end of every run.
__device__ float  g_sum[NP_];            // accumulated per-pixel channel sum
__device__ float  g_S[NP_];              // 3x3 box sum
__device__ double g_p1[BOX_GRID], g_p2[BOX_GRID];  // per-block stats partials
__device__ int    g_devList[C_ * KW_CAP];
__device__ int    g_devCnt[C_];          // plain-stored each run by wscan
__device__ int    g_anyDev;              // written by k_box last block
__device__ float  g_a[C_], g_b[C_];      // fused BN scale/shift
__device__ unsigned int g_ticket;        // = 0 initially; self-restores to 0

__device__ __forceinline__ float sgn(float v) {
    return (float)((v > 0.0f) - (v < 0.0f));
}

// ---- L2-policy accesses: ALL evict hints require 256-bit (.v8.b32) on sm_103a.
__device__ __forceinline__ void ldg_evict_last8(const float* p, float* v) {
    asm volatile("ld.global.nc.L2::evict_last.v8.b32 {%0,%1,%2,%3,%4,%5,%6,%7}, [%8];"
                 : "=f"(v[0]), "=f"(v[1]), "=f"(v[2]), "=f"(v[3]),
                   "=f"(v[4]), "=f"(v[5]), "=f"(v[6]), "=f"(v[7]) : "l"(p));
}
__device__ __forceinline__ void ldg_evict_first8(const float* p, float* v) {
    asm volatile("ld.global.nc.L2::evict_first.v8.b32 {%0,%1,%2,%3,%4,%5,%6,%7}, [%8];"
                 : "=f"(v[0]), "=f"(v[1]), "=f"(v[2]), "=f"(v[3]),
                   "=f"(v[4]), "=f"(v[5]), "=f"(v[6]), "=f"(v[7]) : "l"(p));
}
__device__ __forceinline__ void stg_evict_first8(float* p, const float* v) {
    asm volatile("st.global.L2::evict_first.v8.b32 [%0], {%1,%2,%3,%4,%5,%6,%7,%8};"
                 :: "l"(p), "f"(v[0]), "f"(v[1]), "f"(v[2]), "f"(v[3]),
                    "f"(v[4]), "f"(v[5]), "f"(v[6]), "f"(v[7]) : "memory");
}
// vector reduction: 4 floats per RED instruction (sm_90+ PTX)
__device__ __forceinline__ void red_add_v4(float* p, const float* v) {
    asm volatile("red.global.add.v4.f32 [%0], {%1,%2,%3,%4};"
                 :: "l"(p), "f"(v[0]), "f"(v[1]), "f"(v[2]), "f"(v[3]) : "memory");
}

// ---------------- kernel 1: csum (392 blocks) + wscan (256 blocks), fused ---
__global__ void __launch_bounds__(256) k_csum_wscan(const float* __restrict__ x,
                                                    const float* __restrict__ w) {
    int b = blockIdx.x;
    if (b < CSUM_TOTAL) {
        int pl = b / CSUM_BLOCKS;
        int q  = (b - pl * CSUM_BLOCKS) * 256 + threadIdx.x;   // oct index, exact
        int p8 = q * 8;
        int n  = p8 / HW_;
        int hw = p8 - n * HW_;
        const float* xp = x + ((size_t)n * C_ + pl * CPER) * HW_ + hw;
        float acc[8] = {0.f, 0.f, 0.f, 0.f, 0.f, 0.f, 0.f, 0.f};
#pragma unroll
        for (int c = 0; c < CPER; c++) {
            float v[8];
            ldg_evict_last8(xp + (size_t)c * HW_, v);   // keep x L2-resident
#pragma unroll
            for (int l = 0; l < 8; l++) acc[l] += sgn(v[l]);
        }
        // accumulate into single plane (exact: integer-valued floats);
        // 2 vector REDs instead of 8 scalar atomics
        red_add_v4(g_sum + p8,     acc);
        red_add_v4(g_sum + p8 + 4, acc + 4);
        return;
    }
    // ---- weight-deviant compaction, one block per output channel ----
    __shared__ int cnt;
    int o = b - CSUM_TOTAL;
    if (threadIdx.x == 0) cnt = 0;
    __syncthreads();
    const float* wo = w + (size_t)o * (C_ * 9);
#pragma unroll
    for (int j = 0; j < 9; j++) {
        int i = threadIdx.x * 9 + j;         // i < 2304
        float v = wo[i];
        int s = (v > 0.0f) - (v < 0.0f);     // jnp.sign
        int delta = s - 1;
        if (delta != 0) {
            int c = i / 9, k = i - c * 9;
            int slot = atomicAdd(&cnt, 1);   // shared atomic only
            g_devList[o * KW_CAP + slot] = (c << 6) | (k << 2) | (delta + 2);
        }
    }
    __syncthreads();
    if (threadIdx.x == 0) g_devCnt[o] = cnt;
}

__device__ __forceinline__ float signx_at(const float* __restrict__ x,
                                          int n, int c, int hh, int ww) {
    if (hh < 0 || hh >= H_ || ww < 0 || ww >= W_) return 0.0f;
    float v = x[((size_t)n * C_ + c) * HW_ + hh * W_ + ww];
    return sgn(v);
}

// ---------------- kernel 2: 3x3 box over SINGLE plane + stats + params ------
__global__ void __launch_bounds__(BOX_BLOCK) k_box(const float* __restrict__ x,
                                                   const float* __restrict__ gamma,
                                                   const float* __restrict__ beta) {
    int q  = blockIdx.x * BOX_BLOCK + threadIdx.x;   // exact: 196*128 = QUADS
    int p4 = q * 4;
    int n  = p4 / HW_;
    int hw = p4 - n * HW_;
    int h  = hw / W_, w0 = hw - h * W_;              // w0 % 4 == 0

    float v0 = 0.f, v1 = 0.f, v2 = 0.f, v3 = 0.f, v4 = 0.f, v5 = 0.f;
    const float* base = g_sum + n * HW_;
#pragma unroll
    for (int dh = -1; dh <= 1; dh++) {
        int hh = h + dh;
        if ((unsigned)hh < (unsigned)H_) {
            const float* r = base + hh * W_;
            if (w0 > 0)       v0 += r[w0 - 1];
            float4 m = *reinterpret_cast<const float4*>(r + w0);
            v1 += m.x; v2 += m.y; v3 += m.z; v4 += m.w;
            if (w0 + 4 < W_)  v5 += r[w0 + 4];
        }
    }
    float S0 = v0 + v1 + v2;
    float S1 = v1 + v2 + v3;
    float S2 = v2 + v3 + v4;
    float S3 = v3 + v4 + v5;
    float4 o; o.x = S0; o.y = S1; o.z = S2; o.w = S3;
    *reinterpret_cast<float4*>(g_S + p4) = o;

    // block stats partials (double, plain store)
    double s1 = (double)S0 + (double)S1 + (double)S2 + (double)S3;
    double s2 = (double)S0 * S0 + (double)S1 * S1 + (double)S2 * S2 + (double)S3 * S3;
#pragma unroll
    for (int off = 16; off > 0; off >>= 1) {
        s1 += __shfl_xor_sync(0xffffffffu, s1, off);
        s2 += __shfl_xor_sync(0xffffffffu, s2, off);
    }
    __shared__ double w1[4], w2[4];
    int lane = threadIdx.x & 31, warp = threadIdx.x >> 5;
    if (lane == 0) { w1[warp] = s1; w2[warp] = s2; }
    __syncthreads();
    __shared__ bool isLast;
    if (threadIdx.x == 0) {
        g_p1[blockIdx.x] = w1[0] + w1[1] + w1[2] + w1[3];
        g_p2[blockIdx.x] = w2[0] + w2[1] + w2[2] + w2[3];
        __threadfence();
        unsigned int t = atomicAdd(&g_ticket, 1u);
        isLast = (t == BOX_GRID - 1);
        if (isLast) g_ticket = 0;            // self-restore for graph replay
    }
    __syncthreads();
    if (!isLast) return;

    // ---- last block: reduce 196 partials, write BN params ----
    int t = threadIdx.x;
    __shared__ double r1[BOX_BLOCK], r2[BOX_BLOCK];
    double a1 = 0.0, a2 = 0.0;
    for (int i = t; i < BOX_GRID; i += BOX_BLOCK) { a1 += g_p1[i]; a2 += g_p2[i]; }
    r1[t] = a1; r2[t] = a2;
    __syncthreads();
#pragma unroll
    for (int off = BOX_BLOCK / 2; off > 0; off >>= 1) {
        if (t < off) { r1[t] += r1[t + off]; r2[t] += r2[t + off]; }
        __syncthreads();
    }
    double baseSum = r1[0], baseSum2 = r2[0];

    __shared__ int anyDev;
    if (t == 0) anyDev = 0;
    __syncthreads();
    if (t < 128) {
        if (g_devCnt[t] != 0 || g_devCnt[t + 128] != 0) atomicAdd(&anyDev, 1);
    }
    __syncthreads();
    if (t == 0) g_anyDev = anyDev;

    const double M = (double)NP_;
#pragma unroll
    for (int rep = 0; rep < C_ / BOX_BLOCK; rep++) {   // 2 channels per thread
        int c = rep * BOX_BLOCK + t;
        double c1 = 0.0, c2 = 0.0, c3 = 0.0;
        int cnt = g_devCnt[c];
        if (cnt != 0) {                      // never-taken serial fallback
            const int* list = g_devList + c * KW_CAP;
            for (int p = 0; p < NP_; p++) {
                int nn = p / HW_;
                int phw = p - nn * HW_;
                int ph = phw / W_, pw = phw - (phw / W_) * W_;
                float corr = 0.0f;
                for (int j = 0; j < cnt; j++) {
                    int e = list[j];
                    int cin = e >> 6;
                    int k   = (e >> 2) & 15;
                    float delta = (float)((e & 3) - 2);
                    corr += delta * signx_at(x, nn, cin, ph + k / 3 - 1, pw + k % 3 - 1);
                }
                c1 += (double)corr;
                c2 += (double)g_S[p] * (double)corr;
                c3 += (double)corr * (double)corr;
            }
        }
        double mean = (baseSum + c1) / M;
        double ex2  = (baseSum2 + 2.0 * c2 + c3) / M;
        double var  = ex2 - mean * mean;
        float a = gamma[c] * (float)(1.0 / sqrt(var + 1e-5));
        g_a[c] = a;
        g_b[c] = beta[c] - a * (float)mean;
    }
}

// ---------------- kernel 3: normalize + residual (256-bit, MLP=4) -----------
// grid (49, C_/OCHUNK): one 8-float g_S oct serves OCHUNK channels.
// blockIdx.y == 0 additionally re-zeroes g_sum for the next graph replay.
__global__ void __launch_bounds__(256) k_out(const float* __restrict__ x,
                                             float* __restrict__ out) {
    int q = blockIdx.x * 256 + threadIdx.x;      // oct index, exact grid
    int c0 = blockIdx.y * OCHUNK;
    int p8 = q * 8;
    int n  = p8 / HW_;
    int hw = p8 - n * HW_;

    if (blockIdx.y == 0) {                       // reset accumulator plane
        float4 z; z.x = 0.f; z.y = 0.f; z.z = 0.f; z.w = 0.f;
        *reinterpret_cast<float4*>(g_sum + p8)     = z;
        *reinterpret_cast<float4*>(g_sum + p8 + 4) = z;
    }

    float Ss[8];
    *reinterpret_cast<float4*>(Ss)     = *reinterpret_cast<const float4*>(g_S + p8);
    *reinterpret_cast<float4*>(Ss + 4) = *reinterpret_cast<const float4*>(g_S + p8 + 4);
    size_t base = ((size_t)n * C_ + c0) * HW_ + hw;

    if (g_anyDev == 0) {
        // ---- fast path: 256-bit loads/stores, front-batched ----
        float xs[OCHUNK][8];
#pragma unroll
        for (int cc = 0; cc < OCHUNK; cc++)
            ldg_evict_first8(x + base + (size_t)cc * HW_, xs[cc]);  // consume + release
        float av[OCHUNK], bv[OCHUNK];
#pragma unroll
        for (int cc = 0; cc < OCHUNK; cc++) { av[cc] = g_a[c0 + cc]; bv[cc] = g_b[c0 + cc]; }
#pragma unroll
        for (int cc = 0; cc < OCHUNK; cc++) {
            float a = av[cc], b = bv[cc];
            float o8[8];
#pragma unroll
            for (int l = 0; l < 8; l++)
                o8[l] = fmaf(a, Ss[l], b) + xs[cc][l];
            stg_evict_first8(out + base + (size_t)cc * HW_, o8);
        }
        return;
    }

    // ---- slow path (weight deviants exist) ----
    for (int cc = 0; cc < OCHUNK; cc++) {
        int c = c0 + cc;
        float a = g_a[c], b = g_b[c];
        float Sc[8];
#pragma unroll
        for (int l = 0; l < 8; l++) Sc[l] = Ss[l];
        int cnt = g_devCnt[c];
        if (cnt != 0) {
            const int* list = g_devList + c * KW_CAP;
            int h = hw / W_, w0 = hw - (hw / W_) * W_;
            for (int j = 0; j < cnt; j++) {
                int e = list[j];
                int cin = e >> 6;
                int k   = (e >> 2) & 15;
                float delta = (float)((e & 3) - 2);
                int dh = k / 3 - 1, dw = k % 3 - 1;
#pragma unroll
                for (int l = 0; l < 8; l++)
                    Sc[l] += delta * signx_at(x, n, cin, h + dh, w0 + l + dw);
            }
        }
        size_t idx = base + (size_t)cc * HW_;
#pragma unroll
        for (int l = 0; l < 8; l++)
            out[idx + l] = fmaf(a, Sc[l], b) + x[idx + l];
    }
}

// ---------------- launch -----------------------------------------------------
extern "C" void kernel_launch(void* const* d_in, const int* in_sizes, int n_in,
                              void* d_out, int out_size) {
    const float* x     = (const float*)d_in[0];
    const float* w     = (const float*)d_in[1];
    const float* gamma = (const float*)d_in[2];
    const float* beta  = (const float*)d_in[3];
    float* out = (float*)d_out;

    k_csum_wscan<<<CSUM_TOTAL + C_, 256>>>(x, w);   // 648 blocks
    k_box<<<BOX_GRID, BOX_BLOCK>>>(x, gamma, beta); // 196 x 128, exact
    {
        dim3 grid(OUT_BLOCKS, C_ / OCHUNK);         // (49, 64), exact
        k_out<<<grid, 256>>>(x, out);
    }
}